// round 4
// baseline (speedup 1.0000x reference)
#include <cuda_runtime.h>
#include <cstdint>

#define SEQ     512
#define INP     5
#define HID     64
#define RPP     7                 // batch rows per warp-pair
#define PAIRS   8                 // warp-pairs per CTA
#define TB      (RPP * PAIRS)     // 56 batch rows per CTA
#define PAD     68                // padded row length (floats), conflict-free
#define THREADS 512
#define PSZ     1024              // floats per pair region: 2*7*68 h + 2*36 x

// packed f32x2 helpers (Blackwell native paired fp32 math)
__device__ __forceinline__ void fma2(unsigned long long& d,
                                     unsigned long long a,
                                     unsigned long long b) {
    asm("fma.rn.f32x2 %0, %1, %2, %0;" : "+l"(d) : "l"(a), "l"(b));
}
__device__ __forceinline__ float2 unpack2(unsigned long long v) {
    float lo, hi;
    asm("mov.b64 {%0, %1}, %2;" : "=f"(lo), "=f"(hi) : "l"(v));
    return make_float2(lo, hi);
}

__device__ __forceinline__ float sigmoid_f(float x) {
    return __fdividef(1.f, 1.f + __expf(-x));
}
__device__ __forceinline__ float tanh_f(float x) {
    return __fdividef(2.f, 1.f + __expf(-2.f * x)) - 1.f;
}

// ---------------------------------------------------------------------------
// One CTA = 512 threads = 8 independent warp-PAIRS (verified R2 structure).
// Each pair owns RPP=7 batch rows; thread (lane, half) owns hidden j and
// computes all 4 gates for all 7 rows -> c/h update register-local. Pairs
// sync only among their own 64 threads via named barriers.
// NEW (single delta vs R2): one-time per-pair phase stagger so the pairs
// resident on the same SMSPs run ~1/8-step offset from each other; each
// pair's MUFU epilogue then overlaps other pairs' FMA matmul phases.
// ---------------------------------------------------------------------------
__global__ void __launch_bounds__(THREADS, 1)
lstm_kernel(const float* __restrict__ inputs,  // [B, SEQ, INP]
            const float* __restrict__ W_ih,    // [256, INP]
            const float* __restrict__ W_hh,    // [256, HID]
            const float* __restrict__ b_ih,    // [256]
            const float* __restrict__ b_hh,    // [256]
            const float* __restrict__ fc_w,    // [1, HID]
            const float* __restrict__ fc_b,    // [1]
            float* __restrict__ out,           // [B, 1]
            int batch)
{
    extern __shared__ float sm[];
    float* Wsh = sm;                                   // 256*PAD floats

    const int t    = threadIdx.x;
    const int lane = t & 31;
    const int warp = t >> 5;
    const int pair = warp >> 1;                        // 0..7
    const int half = warp & 1;
    const int j    = lane + (half << 5);               // 0..63 within pair

    float* Hp = Wsh + 256 * PAD + pair * PSZ;          // 2 x (RPP*PAD) h bufs
    float* Xp = Hp + 2 * RPP * PAD;                    // 2 x 36 x bufs

    const int rowbase = blockIdx.x * TB + pair * RPP;

    // Stage W_hh into padded smem (all 512 threads)
    for (int idx = t; idx < 256 * HID; idx += THREADS) {
        int r = idx >> 6, k = idx & 63;
        Wsh[r * PAD + k] = W_hh[idx];
    }
    // h0 = 0 (buffer 0) for this pair
    for (int idx = j; idx < RPP * PAD; idx += 64) Hp[idx] = 0.f;
    // Prefetch x for step 0 into x-buffer 0
    if (j < RPP * INP) {
        int b = j / INP, i = j - b * INP;
        int row = min(rowbase + b, batch - 1);
        Xp[b * INP + i] = inputs[(size_t)row * (SEQ * INP) + i];
    }

    // Per-thread constants: W_ih rows + combined bias for (gate g, hidden j)
    float wih[4][INP], bias[4];
#pragma unroll
    for (int g = 0; g < 4; ++g) {
        int r = g * HID + j;
#pragma unroll
        for (int i = 0; i < INP; ++i) wih[g][i] = W_ih[r * INP + i];
        bias[g] = b_ih[r] + b_hh[r];
    }

    float c[RPP];
#pragma unroll
    for (int b = 0; b < RPP; ++b) c[b] = 0.f;

    __syncthreads();   // W + all pair buffers staged

    // One-time phase stagger: pair p delays ~p * 1600 cycles (dependent FFMA
    // chain, lat 4/iter). Pairs never resync CTA-wide, so offsets persist.
    if (pair != 0) {
        float z = (float)(t + 1);
        const int iters = pair * 400;
        for (int i = 0; i < iters; ++i)
            asm volatile("fma.rn.f32 %0, %0, 0f3F7FFF58, 0f33800000;" : "+f"(z));
        asm volatile("" :: "f"(z));   // keep the chain live
    }

    const float* Wj = Wsh + j * PAD;    // gate g row at + g*HID*PAD

    for (int s = 0; s < SEQ; ++s) {
        const float* hin  = Hp + (s & 1) * (RPP * PAD);
        float*       hout = Hp + ((s + 1) & 1) * (RPP * PAD);
        const float* xin  = Xp + (s & 1) * 36;
        float*       xnx  = Xp + ((s + 1) & 1) * 36;

        // Prefetch next step's inputs for this pair (35 scalars, 64 threads)
        if (s + 1 < SEQ && j < RPP * INP) {
            int b = j / INP, i = j - b * INP;
            int row = min(rowbase + b, batch - 1);
            xnx[b * INP + i] = inputs[(size_t)row * (SEQ * INP)
                                      + (size_t)(s + 1) * INP + i];
        }

        // gates[b][g] = sum_k W_hh[g*64+j][k] * h[b][k]   (packed f32x2)
        unsigned long long acc[RPP][4];
#pragma unroll
        for (int b = 0; b < RPP; ++b)
#pragma unroll
            for (int g = 0; g < 4; ++g) acc[b][g] = 0ull;

#pragma unroll
        for (int k4 = 0; k4 < 16; ++k4) {
            ulonglong2 w0 = ((const ulonglong2*)(Wj + 0 * HID * PAD))[k4];
            ulonglong2 w1 = ((const ulonglong2*)(Wj + 1 * HID * PAD))[k4];
            ulonglong2 w2 = ((const ulonglong2*)(Wj + 2 * HID * PAD))[k4];
            ulonglong2 w3 = ((const ulonglong2*)(Wj + 3 * HID * PAD))[k4];
#pragma unroll
            for (int b = 0; b < RPP; ++b) {
                ulonglong2 h = ((const ulonglong2*)(hin + b * PAD))[k4];
                fma2(acc[b][0], w0.x, h.x); fma2(acc[b][0], w0.y, h.y);
                fma2(acc[b][1], w1.x, h.x); fma2(acc[b][1], w1.y, h.y);
                fma2(acc[b][2], w2.x, h.x); fma2(acc[b][2], w2.y, h.y);
                fma2(acc[b][3], w3.x, h.x); fma2(acc[b][3], w3.y, h.y);
            }
        }

        // Epilogue: x-projection + biases, activations, c/h update
#pragma unroll
        for (int b = 0; b < RPP; ++b) {
            float x0 = xin[b * INP + 0], x1 = xin[b * INP + 1],
                  x2 = xin[b * INP + 2], x3 = xin[b * INP + 3],
                  x4 = xin[b * INP + 4];
            float gate[4];
#pragma unroll
            for (int g = 0; g < 4; ++g) {
                float2 p = unpack2(acc[b][g]);
                gate[g] = p.x + p.y + bias[g]
                        + x0 * wih[g][0] + x1 * wih[g][1] + x2 * wih[g][2]
                        + x3 * wih[g][3] + x4 * wih[g][4];
            }
            float ig = sigmoid_f(gate[0]);
            float fg = sigmoid_f(gate[1]);
            float gg = tanh_f(gate[2]);
            float og = sigmoid_f(gate[3]);
            float cn = fg * c[b] + ig * gg;
            c[b] = cn;
            hout[b * PAD + j] = og * tanh_f(cn);
        }

        // Pair-local sync: only the 64 threads sharing these batch rows
        asm volatile("bar.sync %0, 64;" :: "r"(pair) : "memory");
    }

    // Final FC + leaky ReLU. Last write was into buffer (SEQ & 1) == 0.
    const float* hf  = Hp;
    const float  fw0 = fc_w[lane];
    const float  fw1 = fc_w[lane + 32];
    const float  fb  = fc_b[0];
    const int    b0  = half ? 4 : 0;
    const int    b1  = half ? RPP : 4;
    for (int b = b0; b < b1; ++b) {
        float p = hf[b * PAD + lane] * fw0 + hf[b * PAD + lane + 32] * fw1;
#pragma unroll
        for (int off = 16; off > 0; off >>= 1)
            p += __shfl_xor_sync(0xffffffffu, p, off);
        if (lane == 0) {
            int row = rowbase + b;
            if (row < batch) {
                float v = p + fb;
                out[row] = (v >= 0.f) ? v : 0.01f * v;
            }
        }
    }
}

extern "C" void kernel_launch(void* const* d_in, const int* in_sizes, int n_in,
                              void* d_out, int out_size) {
    const float* inputs = (const float*)d_in[0];
    const float* W_ih   = (const float*)d_in[1];
    const float* W_hh   = (const float*)d_in[2];
    const float* b_ih   = (const float*)d_in[3];
    const float* b_hh   = (const float*)d_in[4];
    const float* fc_w   = (const float*)d_in[5];
    const float* fc_b   = (const float*)d_in[6];
    float*       out    = (float*)d_out;

    const int batch = in_sizes[0] / (SEQ * INP);                 // 8192
    const int grid  = (batch + TB - 1) / TB;                     // 147
    const int smem  = (256 * PAD + PAIRS * PSZ) * (int)sizeof(float); // 102400 B

    cudaFuncSetAttribute(lstm_kernel,
                         cudaFuncAttributeMaxDynamicSharedMemorySize, smem);
    lstm_kernel<<<grid, THREADS, smem>>>(inputs, W_ih, W_hh, b_ih, b_hh,
                                         fc_w, fc_b, out, batch);
}

// round 6
// speedup vs baseline: 2.1605x; 2.1605x over previous
#include <cuda_runtime.h>
#include <cuda_bf16.h>
#include <cstdint>

#define SEQ     512
#define INP     5
#define HID     64
#define NB      56          // batch cols per CTA
#define NTL     7           // n-tiles (8 cols each)
#define KTL     5           // k-tiles (16 each) -> KE=80
#define KE      80
#define BPAD    88          // bf16 per B column (44 words = 12 mod 32: conflict-free)
#define THREADS 256

struct SmemT {
    __align__(16) __nv_bfloat16 B[2][2][NB * BPAD];  // [parity][0=hi,1=lo][col][k]
};

__device__ __forceinline__ uint32_t pack_bf16(float lo, float hi) {
    __nv_bfloat162 t = __floats2bfloat162_rn(lo, hi);   // .x=lo (lower 16 bits)
    return *(uint32_t*)&t;
}
__device__ __forceinline__ void split2(float v, float& hi, float& lo) {
    hi = __bfloat162float(__float2bfloat16(v));
    lo = v - hi;
}
__device__ __forceinline__ float sigmoid_f(float x) {
    return __fdividef(1.f, 1.f + __expf(-x));
}
__device__ __forceinline__ float tanh_f(float x) {
    return __fdividef(2.f, 1.f + __expf(-2.f * x)) - 1.f;
}

// mma.sync m16n8k16 row.col bf16 -> f32, D += A*B
__device__ __forceinline__ void mma16816(float* c, const uint32_t* a, const uint32_t* b) {
    asm volatile(
        "mma.sync.aligned.m16n8k16.row.col.f32.bf16.bf16.f32 "
        "{%0,%1,%2,%3}, {%4,%5,%6,%7}, {%8,%9}, {%0,%1,%2,%3};"
        : "+f"(c[0]), "+f"(c[1]), "+f"(c[2]), "+f"(c[3])
        : "r"(a[0]), "r"(a[1]), "r"(a[2]), "r"(a[3]), "r"(b[0]), "r"(b[1]));
}

// Extended weight matrix element: W_ext[m][k], m permuted so that within a
// warp's m-pair (tiles 2w, 2w+1) each thread's 4 C rows = i,f,g,o of one j.
//   j = (m>>5)*8 + (m&7),  g = 2*((m>>4)&1) + ((m>>3)&1)
__device__ float wext(const float* W_hh, const float* W_ih,
                      const float* b_ih, const float* b_hh, int m, int k) {
    int j   = ((m >> 5) << 3) | (m & 7);
    int g   = (((m >> 4) & 1) << 1) | ((m >> 3) & 1);
    int row = g * HID + j;
    if (k < HID)            return W_hh[row * HID + k];
    if (k < HID + INP)      return W_ih[row * INP + (k - HID)];
    if (k == HID + INP)     return b_ih[row] + b_hh[row];   // bias column
    return 0.f;
}

// ---------------------------------------------------------------------------
// HMMA LSTM. Per CTA: 56 batch cols, 512 steps. 8 warps; warp w owns hidden
// j in [8w, 8w+8) for ALL 56 cols. W_ext fragments resident in registers
// (hi+lo bf16 split); B = [h|x|1|0] hi/lo streamed from smem, double-buffered
// by step parity; 3 MMA split-terms for ~2^-17 matmul error.
// ---------------------------------------------------------------------------
__global__ void __launch_bounds__(THREADS, 1)
lstm_hmma_kernel(const float* __restrict__ inputs,  // [B, SEQ, INP]
                 const float* __restrict__ W_ih,    // [256, INP]
                 const float* __restrict__ W_hh,    // [256, HID]
                 const float* __restrict__ b_ih,    // [256]
                 const float* __restrict__ b_hh,    // [256]
                 const float* __restrict__ fc_w,    // [1, HID]
                 const float* __restrict__ fc_b,    // [1]
                 float* __restrict__ out,           // [B, 1]
                 int batch)
{
    __shared__ SmemT sm;

    const int t    = threadIdx.x;
    const int lane = t & 31;
    const int w    = t >> 5;
    const int gid  = lane >> 2;          // fragment row group 0..7
    const int tig  = lane & 3;           // fragment col group 0..3
    const int jm   = (w << 3) | gid;     // this thread's hidden index
    const int batch0 = blockIdx.x * NB;

    // ---- init smem: zero all buffers, set bias row (k=69) = 1.0 in hi bufs
    for (int idx = t; idx < 2 * 2 * NB * BPAD / 2; idx += THREADS)
        ((uint32_t*)sm.B)[idx] = 0u;
    __syncthreads();
    if (t < NB) {
        sm.B[0][0][t * BPAD + HID + INP] = __float2bfloat16(1.0f);
        sm.B[1][0][t * BPAD + HID + INP] = __float2bfloat16(1.0f);
    }

    // x(0) into parity-0 buffer rows 64..68
    for (int q = t; q < NB * INP; q += THREADS) {
        int col = q / INP, i = q - col * INP;
        int row = min(batch0 + col, batch - 1);
        float xv = inputs[(size_t)row * (SEQ * INP) + i];
        float xh, xl; split2(xv, xh, xl);
        sm.B[0][0][col * BPAD + HID + i] = __float2bfloat16(xh);
        sm.B[0][1][col * BPAD + HID + i] = __float2bfloat16(xl);
    }

    // ---- load W_ext fragments into registers (hi/lo), one-time
    uint32_t ahi[2][KTL][4], alo[2][KTL][4];
#pragma unroll
    for (int mt = 0; mt < 2; ++mt) {
        const int mbase = ((w << 1) | mt) << 4;
#pragma unroll
        for (int kt = 0; kt < KTL; ++kt) {
#pragma unroll
            for (int cp = 0; cp < 2; ++cp) {          // col pair: k+0/1 or k+8/9
#pragma unroll
                for (int rr = 0; rr < 2; ++rr) {      // row gid or gid+8
                    int m  = mbase + gid + rr * 8;
                    int k0 = kt * 16 + 2 * tig + cp * 8;
                    float v0 = wext(W_hh, W_ih, b_ih, b_hh, m, k0);
                    float v1 = wext(W_hh, W_ih, b_ih, b_hh, m, k0 + 1);
                    float h0, l0, h1, l1;
                    split2(v0, h0, l0);
                    split2(v1, h1, l1);
                    ahi[mt][kt][cp * 2 + rr] = pack_bf16(h0, h1);
                    alo[mt][kt][cp * 2 + rr] = pack_bf16(l0, l1);
                }
            }
        }
    }

    // x prefetch ownership: indices t and t+256 (< NB*INP = 280)
    const int  q1   = t + THREADS;
    const bool hq1  = q1 < NB * INP;
    const int  c0i  = t / INP,  i0 = t - c0i * INP;
    const int  c1i  = hq1 ? q1 / INP : 0, i1 = hq1 ? q1 - c1i * INP : 0;
    const float* xp0 = inputs + (size_t)min(batch0 + c0i, batch - 1) * (SEQ * INP) + i0;
    const float* xp1 = inputs + (size_t)min(batch0 + c1i, batch - 1) * (SEQ * INP) + i1;

    float cst[2 * NTL];
#pragma unroll
    for (int q = 0; q < 2 * NTL; ++q) cst[q] = 0.f;

    __syncthreads();

    for (int s = 0; s < SEQ; ++s) {
        // prefetch next x
        float xv0 = 0.f, xv1 = 0.f;
        const bool dox = (s + 1 < SEQ);
        if (dox) {
            xv0 = __ldg(xp0 + (size_t)(s + 1) * INP);
            if (hq1) xv1 = __ldg(xp1 + (size_t)(s + 1) * INP);
        }

        const __nv_bfloat16* BH = sm.B[s & 1][0];
        const __nv_bfloat16* BL = sm.B[s & 1][1];

        float cacc[2][NTL][4];
#pragma unroll
        for (int mt = 0; mt < 2; ++mt)
#pragma unroll
            for (int nt = 0; nt < NTL; ++nt)
#pragma unroll
                for (int q = 0; q < 4; ++q) cacc[mt][nt][q] = 0.f;

#pragma unroll
        for (int nt = 0; nt < NTL; ++nt) {
            const int ncol = nt * 8 + gid;
            const uint32_t* colH = (const uint32_t*)(BH + ncol * BPAD);
            const uint32_t* colL = (const uint32_t*)(BL + ncol * BPAD);
            uint32_t bh[KTL][2], bl[KTL][2];
#pragma unroll
            for (int kt = 0; kt < KTL; ++kt) {
                bh[kt][0] = colH[kt * 8 + tig];
                bh[kt][1] = colH[kt * 8 + tig + 4];
                bl[kt][0] = colL[kt * 8 + tig];
                bl[kt][1] = colL[kt * 8 + tig + 4];
            }
#pragma unroll
            for (int mt = 0; mt < 2; ++mt)
#pragma unroll
                for (int kt = 0; kt < KTL; ++kt) {
                    mma16816(cacc[mt][nt], ahi[mt][kt], bh[kt]);
                    mma16816(cacc[mt][nt], ahi[mt][kt], bl[kt]);
                    mma16816(cacc[mt][nt], alo[mt][kt], bh[kt]);
                }
        }

        // epilogue: cells (j=jm, col = nt*8 + 2tig + q), all gates in-thread
        __nv_bfloat16* WH = sm.B[(s + 1) & 1][0];
        __nv_bfloat16* WL = sm.B[(s + 1) & 1][1];
#pragma unroll
        for (int nt = 0; nt < NTL; ++nt) {
#pragma unroll
            for (int q = 0; q < 2; ++q) {
                const float gi = cacc[0][nt][q];
                const float gf = cacc[0][nt][2 + q];
                const float gg = cacc[1][nt][q];
                const float go = cacc[1][nt][2 + q];
                const float ig = sigmoid_f(gi);
                const float fg = sigmoid_f(gf);
                const float gt = tanh_f(gg);
                const float og = sigmoid_f(go);
                const int  ci = nt * 2 + q;
                const float cn = fg * cst[ci] + ig * gt;
                cst[ci] = cn;
                const float hv = og * tanh_f(cn);
                float hh, hl; split2(hv, hh, hl);
                const int col = nt * 8 + 2 * tig + q;
                WH[col * BPAD + jm] = __float2bfloat16(hh);
                WL[col * BPAD + jm] = __float2bfloat16(hl);
            }
        }

        // stash next x into next-parity buffer
        if (dox) {
            float xh, xl;
            split2(xv0, xh, xl);
            WH[c0i * BPAD + HID + i0] = __float2bfloat16(xh);
            WL[c0i * BPAD + HID + i0] = __float2bfloat16(xl);
            if (hq1) {
                split2(xv1, xh, xl);
                WH[c1i * BPAD + HID + i1] = __float2bfloat16(xh);
                WL[c1i * BPAD + HID + i1] = __float2bfloat16(xl);
            }
        }
        __syncthreads();
    }

    // ---- final FC + leaky ReLU; h(512) is in parity-0 buffer (hi+lo)
    const __nv_bfloat16* FH = sm.B[0][0];
    const __nv_bfloat16* FL = sm.B[0][1];
    const float fw0 = fc_w[lane], fw1 = fc_w[lane + 32];
    const float fb  = fc_b[0];
#pragma unroll
    for (int q = 0; q < NTL; ++q) {
        const int col = w * NTL + q;
        float hA = __bfloat162float(FH[col * BPAD + lane])
                 + __bfloat162float(FL[col * BPAD + lane]);
        float hB = __bfloat162float(FH[col * BPAD + lane + 32])
                 + __bfloat162float(FL[col * BPAD + lane + 32]);
        float p = hA * fw0 + hB * fw1;
#pragma unroll
        for (int off = 16; off > 0; off >>= 1)
            p += __shfl_xor_sync(0xffffffffu, p, off);
        if (lane == 0) {
            const int row = batch0 + col;
            if (row < batch) {
                const float v = p + fb;
                out[row] = (v >= 0.f) ? v : 0.01f * v;
            }
        }
    }
}

extern "C" void kernel_launch(void* const* d_in, const int* in_sizes, int n_in,
                              void* d_out, int out_size) {
    const float* inputs = (const float*)d_in[0];
    const float* W_ih   = (const float*)d_in[1];
    const float* W_hh   = (const float*)d_in[2];
    const float* b_ih   = (const float*)d_in[3];
    const float* b_hh   = (const float*)d_in[4];
    const float* fc_w   = (const float*)d_in[5];
    const float* fc_b   = (const float*)d_in[6];
    float*       out    = (float*)d_out;

    const int batch = in_sizes[0] / (SEQ * INP);      // 8192
    const int grid  = (batch + NB - 1) / NB;          // 147

    lstm_hmma_kernel<<<grid, THREADS>>>(inputs, W_ih, W_hh, b_ih, b_hh,
                                        fc_w, fc_b, out, batch);
}

// round 7
// speedup vs baseline: 2.6614x; 1.2318x over previous
#include <cuda_runtime.h>
#include <cuda_bf16.h>
#include <cstdint>

#define SEQ     512
#define INP     5
#define HID     64
#define NB      56          // batch cols per CTA
#define NTL     7           // n-tiles (8 cols each)
#define KTL     5           // k-tiles (16 each) -> KE=80
#define KE      80
#define BPAD    88          // bf16 per B column (44 words = 12 mod 32: conflict-free)
#define THREADS 256

struct SmemT {
    __align__(16) __nv_bfloat16 B[2][2][NB * BPAD];  // [parity][0=hi,1=lo][col][k]
};

__device__ __forceinline__ uint32_t pack_bf16(float lo, float hi) {
    __nv_bfloat162 t = __floats2bfloat162_rn(lo, hi);   // .x=lo (lower 16 bits)
    return *(uint32_t*)&t;
}
__device__ __forceinline__ void split2(float v, float& hi, float& lo) {
    hi = __bfloat162float(__float2bfloat16(v));
    lo = v - hi;
}

// Hardware tanh (sm_75+): 1 MUFU op, max err ~1e-4 abs
__device__ __forceinline__ float tanh_hw(float x) {
    float y;
    asm("tanh.approx.f32 %0, %1;" : "=f"(y) : "f"(x));
    return y;
}
__device__ __forceinline__ float sigmoid_f(float x) {
    return fmaf(tanh_hw(0.5f * x), 0.5f, 0.5f);
}
__device__ __forceinline__ float tanh_f(float x) { return tanh_hw(x); }

// mma.sync m16n8k16 row.col bf16 -> f32, D += A*B
__device__ __forceinline__ void mma16816(float* c, const uint32_t* a, const uint32_t* b) {
    asm volatile(
        "mma.sync.aligned.m16n8k16.row.col.f32.bf16.bf16.f32 "
        "{%0,%1,%2,%3}, {%4,%5,%6,%7}, {%8,%9}, {%0,%1,%2,%3};"
        : "+f"(c[0]), "+f"(c[1]), "+f"(c[2]), "+f"(c[3])
        : "r"(a[0]), "r"(a[1]), "r"(a[2]), "r"(a[3]), "r"(b[0]), "r"(b[1]));
}

// Extended weight matrix element: W_ext[m][k], m permuted so that within a
// warp's m-pair (tiles 2w, 2w+1) each thread's 4 C rows = i,f,g,o of one j.
//   j = (m>>5)*8 + (m&7),  g = 2*((m>>4)&1) + ((m>>3)&1)
__device__ float wext(const float* W_hh, const float* W_ih,
                      const float* b_ih, const float* b_hh, int m, int k) {
    int j   = ((m >> 5) << 3) | (m & 7);
    int g   = (((m >> 4) & 1) << 1) | ((m >> 3) & 1);
    int row = g * HID + j;
    if (k < HID)            return W_hh[row * HID + k];
    if (k < HID + INP)      return W_ih[row * INP + (k - HID)];
    if (k == HID + INP)     return b_ih[row] + b_hh[row];   // bias column
    return 0.f;
}

// ---------------------------------------------------------------------------
// HMMA LSTM (verified R6 structure). Single delta vs R6: activations use the
// single-MUFU hardware tanh.approx.f32 (sigmoid via 0.5*tanh(x/2)+0.5),
// halving the per-step MUFU load and removing the exp->rcp latency chain.
// ---------------------------------------------------------------------------
__global__ void __launch_bounds__(THREADS, 1)
lstm_hmma_kernel(const float* __restrict__ inputs,  // [B, SEQ, INP]
                 const float* __restrict__ W_ih,    // [256, INP]
                 const float* __restrict__ W_hh,    // [256, HID]
                 const float* __restrict__ b_ih,    // [256]
                 const float* __restrict__ b_hh,    // [256]
                 const float* __restrict__ fc_w,    // [1, HID]
                 const float* __restrict__ fc_b,    // [1]
                 float* __restrict__ out,           // [B, 1]
                 int batch)
{
    __shared__ SmemT sm;

    const int t    = threadIdx.x;
    const int lane = t & 31;
    const int w    = t >> 5;
    const int gid  = lane >> 2;          // fragment row group 0..7
    const int tig  = lane & 3;           // fragment col group 0..3
    const int jm   = (w << 3) | gid;     // this thread's hidden index
    const int batch0 = blockIdx.x * NB;

    // ---- init smem: zero all buffers, set bias row (k=69) = 1.0 in hi bufs
    for (int idx = t; idx < 2 * 2 * NB * BPAD / 2; idx += THREADS)
        ((uint32_t*)sm.B)[idx] = 0u;
    __syncthreads();
    if (t < NB) {
        sm.B[0][0][t * BPAD + HID + INP] = __float2bfloat16(1.0f);
        sm.B[1][0][t * BPAD + HID + INP] = __float2bfloat16(1.0f);
    }

    // x(0) into parity-0 buffer rows 64..68
    for (int q = t; q < NB * INP; q += THREADS) {
        int col = q / INP, i = q - col * INP;
        int row = min(batch0 + col, batch - 1);
        float xv = inputs[(size_t)row * (SEQ * INP) + i];
        float xh, xl; split2(xv, xh, xl);
        sm.B[0][0][col * BPAD + HID + i] = __float2bfloat16(xh);
        sm.B[0][1][col * BPAD + HID + i] = __float2bfloat16(xl);
    }

    // ---- load W_ext fragments into registers (hi/lo), one-time
    uint32_t ahi[2][KTL][4], alo[2][KTL][4];
#pragma unroll
    for (int mt = 0; mt < 2; ++mt) {
        const int mbase = ((w << 1) | mt) << 4;
#pragma unroll
        for (int kt = 0; kt < KTL; ++kt) {
#pragma unroll
            for (int cp = 0; cp < 2; ++cp) {          // col pair: k+0/1 or k+8/9
#pragma unroll
                for (int rr = 0; rr < 2; ++rr) {      // row gid or gid+8
                    int m  = mbase + gid + rr * 8;
                    int k0 = kt * 16 + 2 * tig + cp * 8;
                    float v0 = wext(W_hh, W_ih, b_ih, b_hh, m, k0);
                    float v1 = wext(W_hh, W_ih, b_ih, b_hh, m, k0 + 1);
                    float h0, l0, h1, l1;
                    split2(v0, h0, l0);
                    split2(v1, h1, l1);
                    ahi[mt][kt][cp * 2 + rr] = pack_bf16(h0, h1);
                    alo[mt][kt][cp * 2 + rr] = pack_bf16(l0, l1);
                }
            }
        }
    }

    // x prefetch ownership: indices t and t+256 (< NB*INP = 280)
    const int  q1   = t + THREADS;
    const bool hq1  = q1 < NB * INP;
    const int  c0i  = t / INP,  i0 = t - c0i * INP;
    const int  c1i  = hq1 ? q1 / INP : 0, i1 = hq1 ? q1 - c1i * INP : 0;
    const float* xp0 = inputs + (size_t)min(batch0 + c0i, batch - 1) * (SEQ * INP) + i0;
    const float* xp1 = inputs + (size_t)min(batch0 + c1i, batch - 1) * (SEQ * INP) + i1;

    float cst[2 * NTL];
#pragma unroll
    for (int q = 0; q < 2 * NTL; ++q) cst[q] = 0.f;

    __syncthreads();

    for (int s = 0; s < SEQ; ++s) {
        // prefetch next x
        float xv0 = 0.f, xv1 = 0.f;
        const bool dox = (s + 1 < SEQ);
        if (dox) {
            xv0 = __ldg(xp0 + (size_t)(s + 1) * INP);
            if (hq1) xv1 = __ldg(xp1 + (size_t)(s + 1) * INP);
        }

        const __nv_bfloat16* BH = sm.B[s & 1][0];
        const __nv_bfloat16* BL = sm.B[s & 1][1];

        float cacc[2][NTL][4];
#pragma unroll
        for (int mt = 0; mt < 2; ++mt)
#pragma unroll
            for (int nt = 0; nt < NTL; ++nt)
#pragma unroll
                for (int q = 0; q < 4; ++q) cacc[mt][nt][q] = 0.f;

#pragma unroll
        for (int nt = 0; nt < NTL; ++nt) {
            const int ncol = nt * 8 + gid;
            const uint32_t* colH = (const uint32_t*)(BH + ncol * BPAD);
            const uint32_t* colL = (const uint32_t*)(BL + ncol * BPAD);
            uint32_t bh[KTL][2], bl[KTL][2];
#pragma unroll
            for (int kt = 0; kt < KTL; ++kt) {
                bh[kt][0] = colH[kt * 8 + tig];
                bh[kt][1] = colH[kt * 8 + tig + 4];
                bl[kt][0] = colL[kt * 8 + tig];
                bl[kt][1] = colL[kt * 8 + tig + 4];
            }
#pragma unroll
            for (int mt = 0; mt < 2; ++mt)
#pragma unroll
                for (int kt = 0; kt < KTL; ++kt) {
                    mma16816(cacc[mt][nt], ahi[mt][kt], bh[kt]);
                    mma16816(cacc[mt][nt], ahi[mt][kt], bl[kt]);
                    mma16816(cacc[mt][nt], alo[mt][kt], bh[kt]);
                }
        }

        // epilogue: cells (j=jm, col = nt*8 + 2tig + q), all gates in-thread
        __nv_bfloat16* WH = sm.B[(s + 1) & 1][0];
        __nv_bfloat16* WL = sm.B[(s + 1) & 1][1];
#pragma unroll
        for (int nt = 0; nt < NTL; ++nt) {
#pragma unroll
            for (int q = 0; q < 2; ++q) {
                const float gi = cacc[0][nt][q];
                const float gf = cacc[0][nt][2 + q];
                const float gg = cacc[1][nt][q];
                const float go = cacc[1][nt][2 + q];
                const float ig = sigmoid_f(gi);
                const float fg = sigmoid_f(gf);
                const float gt = tanh_f(gg);
                const float og = sigmoid_f(go);
                const int  ci = nt * 2 + q;
                const float cn = fg * cst[ci] + ig * gt;
                cst[ci] = cn;
                const float hv = og * tanh_f(cn);
                float hh, hl; split2(hv, hh, hl);
                const int col = nt * 8 + 2 * tig + q;
                WH[col * BPAD + jm] = __float2bfloat16(hh);
                WL[col * BPAD + jm] = __float2bfloat16(hl);
            }
        }

        // stash next x into next-parity buffer
        if (dox) {
            float xh, xl;
            split2(xv0, xh, xl);
            WH[c0i * BPAD + HID + i0] = __float2bfloat16(xh);
            WL[c0i * BPAD + HID + i0] = __float2bfloat16(xl);
            if (hq1) {
                split2(xv1, xh, xl);
                WH[c1i * BPAD + HID + i1] = __float2bfloat16(xh);
                WL[c1i * BPAD + HID + i1] = __float2bfloat16(xl);
            }
        }
        __syncthreads();
    }

    // ---- final FC + leaky ReLU; h(512) is in parity-0 buffer (hi+lo)
    const __nv_bfloat16* FH = sm.B[0][0];
    const __nv_bfloat16* FL = sm.B[0][1];
    const float fw0 = fc_w[lane], fw1 = fc_w[lane + 32];
    const float fb  = fc_b[0];
#pragma unroll
    for (int q = 0; q < NTL; ++q) {
        const int col = w * NTL + q;
        float hA = __bfloat162float(FH[col * BPAD + lane])
                 + __bfloat162float(FL[col * BPAD + lane]);
        float hB = __bfloat162float(FH[col * BPAD + lane + 32])
                 + __bfloat162float(FL[col * BPAD + lane + 32]);
        float p = hA * fw0 + hB * fw1;
#pragma unroll
        for (int off = 16; off > 0; off >>= 1)
            p += __shfl_xor_sync(0xffffffffu, p, off);
        if (lane == 0) {
            const int row = batch0 + col;
            if (row < batch) {
                const float v = p + fb;
                out[row] = (v >= 0.f) ? v : 0.01f * v;
            }
        }
    }
}

extern "C" void kernel_launch(void* const* d_in, const int* in_sizes, int n_in,
                              void* d_out, int out_size) {
    const float* inputs = (const float*)d_in[0];
    const float* W_ih   = (const float*)d_in[1];
    const float* W_hh   = (const float*)d_in[2];
    const float* b_ih   = (const float*)d_in[3];
    const float* b_hh   = (const float*)d_in[4];
    const float* fc_w   = (const float*)d_in[5];
    const float* fc_b   = (const float*)d_in[6];
    float*       out    = (float*)d_out;

    const int batch = in_sizes[0] / (SEQ * INP);      // 8192
    const int grid  = (batch + NB - 1) / NB;          // 147

    lstm_hmma_kernel<<<grid, THREADS>>>(inputs, W_ih, W_hh, b_ih, b_hh,
                                        fc_w, fc_b, out, batch);
}

// round 8
// speedup vs baseline: 2.6887x; 1.0102x over previous
#include <cuda_runtime.h>
#include <cuda_bf16.h>
#include <cstdint>

#define SEQ     512
#define INP     5
#define HID     64
#define NB      56          // batch cols per CTA
#define NTL     7           // n-tiles (8 cols each)
#define KTL     5           // k-tiles (16 each) -> KE=80
#define KE      80
#define BPAD    88          // bf16 per B column (44 words = 12 mod 32: conflict-free)
#define THREADS 256

struct SmemT {
    __align__(16) __nv_bfloat16 B[2][2][NB * BPAD];  // [parity][0=hi,1=lo][col][k]
};

__device__ __forceinline__ uint32_t pack_bf16(float lo, float hi) {
    __nv_bfloat162 t = __floats2bfloat162_rn(lo, hi);   // .x=lo (lower 16 bits)
    return *(uint32_t*)&t;
}
__device__ __forceinline__ void split2(float v, float& hi, float& lo) {
    hi = __bfloat162float(__float2bfloat16(v));
    lo = v - hi;
}

// Hardware tanh (sm_75+): 1 MUFU op, max err ~1e-4 abs
__device__ __forceinline__ float tanh_hw(float x) {
    float y;
    asm("tanh.approx.f32 %0, %1;" : "=f"(y) : "f"(x));
    return y;
}
__device__ __forceinline__ float sigmoid_f(float x) {
    return fmaf(tanh_hw(0.5f * x), 0.5f, 0.5f);
}
__device__ __forceinline__ float tanh_f(float x) { return tanh_hw(x); }

// mma.sync m16n8k16 row.col bf16 -> f32, D += A*B
__device__ __forceinline__ void mma16816(float* c, const uint32_t* a, const uint32_t* b) {
    asm volatile(
        "mma.sync.aligned.m16n8k16.row.col.f32.bf16.bf16.f32 "
        "{%0,%1,%2,%3}, {%4,%5,%6,%7}, {%8,%9}, {%0,%1,%2,%3};"
        : "+f"(c[0]), "+f"(c[1]), "+f"(c[2]), "+f"(c[3])
        : "r"(a[0]), "r"(a[1]), "r"(a[2]), "r"(a[3]), "r"(b[0]), "r"(b[1]));
}

// Extended weight matrix element: W_ext[m][k], m permuted so that within a
// warp's m-pair (tiles 2w, 2w+1) each thread's 4 C rows = i,f,g,o of one j.
//   j = (m>>5)*8 + (m&7),  g = 2*((m>>4)&1) + ((m>>3)&1)
__device__ float wext(const float* W_hh, const float* W_ih,
                      const float* b_ih, const float* b_hh, int m, int k) {
    int j   = ((m >> 5) << 3) | (m & 7);
    int g   = (((m >> 4) & 1) << 1) | ((m >> 3) & 1);
    int row = g * HID + j;
    if (k < HID)            return W_hh[row * HID + k];
    if (k < HID + INP)      return W_ih[row * INP + (k - HID)];
    if (k == HID + INP)     return b_ih[row] + b_hh[row];   // bias column
    return 0.f;
}

// ---------------------------------------------------------------------------
// HMMA LSTM (verified R7 structure). Single delta vs R7: the per-step loops
// are fused so epilogue(nt-1) (MUFU/FMA/STS) issues while the 30 HMMAs of
// n-tile nt drain through the tensor pipe -> MUFU hidden under tensor time.
// ---------------------------------------------------------------------------
__global__ void __launch_bounds__(THREADS, 1)
lstm_hmma_kernel(const float* __restrict__ inputs,  // [B, SEQ, INP]
                 const float* __restrict__ W_ih,    // [256, INP]
                 const float* __restrict__ W_hh,    // [256, HID]
                 const float* __restrict__ b_ih,    // [256]
                 const float* __restrict__ b_hh,    // [256]
                 const float* __restrict__ fc_w,    // [1, HID]
                 const float* __restrict__ fc_b,    // [1]
                 float* __restrict__ out,           // [B, 1]
                 int batch)
{
    __shared__ SmemT sm;

    const int t    = threadIdx.x;
    const int lane = t & 31;
    const int w    = t >> 5;
    const int gid  = lane >> 2;          // fragment row group 0..7
    const int tig  = lane & 3;           // fragment col group 0..3
    const int jm   = (w << 3) | gid;     // this thread's hidden index
    const int batch0 = blockIdx.x * NB;

    // ---- init smem: zero all buffers, set bias row (k=69) = 1.0 in hi bufs
    for (int idx = t; idx < 2 * 2 * NB * BPAD / 2; idx += THREADS)
        ((uint32_t*)sm.B)[idx] = 0u;
    __syncthreads();
    if (t < NB) {
        sm.B[0][0][t * BPAD + HID + INP] = __float2bfloat16(1.0f);
        sm.B[1][0][t * BPAD + HID + INP] = __float2bfloat16(1.0f);
    }

    // x(0) into parity-0 buffer rows 64..68
    for (int q = t; q < NB * INP; q += THREADS) {
        int col = q / INP, i = q - col * INP;
        int row = min(batch0 + col, batch - 1);
        float xv = inputs[(size_t)row * (SEQ * INP) + i];
        float xh, xl; split2(xv, xh, xl);
        sm.B[0][0][col * BPAD + HID + i] = __float2bfloat16(xh);
        sm.B[0][1][col * BPAD + HID + i] = __float2bfloat16(xl);
    }

    // ---- load W_ext fragments into registers (hi/lo), one-time
    uint32_t ahi[2][KTL][4], alo[2][KTL][4];
#pragma unroll
    for (int mt = 0; mt < 2; ++mt) {
        const int mbase = ((w << 1) | mt) << 4;
#pragma unroll
        for (int kt = 0; kt < KTL; ++kt) {
#pragma unroll
            for (int cp = 0; cp < 2; ++cp) {          // col pair: k+0/1 or k+8/9
#pragma unroll
                for (int rr = 0; rr < 2; ++rr) {      // row gid or gid+8
                    int m  = mbase + gid + rr * 8;
                    int k0 = kt * 16 + 2 * tig + cp * 8;
                    float v0 = wext(W_hh, W_ih, b_ih, b_hh, m, k0);
                    float v1 = wext(W_hh, W_ih, b_ih, b_hh, m, k0 + 1);
                    float h0, l0, h1, l1;
                    split2(v0, h0, l0);
                    split2(v1, h1, l1);
                    ahi[mt][kt][cp * 2 + rr] = pack_bf16(h0, h1);
                    alo[mt][kt][cp * 2 + rr] = pack_bf16(l0, l1);
                }
            }
        }
    }

    // x prefetch ownership: indices t and t+256 (< NB*INP = 280)
    const int  q1   = t + THREADS;
    const bool hq1  = q1 < NB * INP;
    const int  c0i  = t / INP,  i0 = t - c0i * INP;
    const int  c1i  = hq1 ? q1 / INP : 0, i1 = hq1 ? q1 - c1i * INP : 0;
    const float* xp0 = inputs + (size_t)min(batch0 + c0i, batch - 1) * (SEQ * INP) + i0;
    const float* xp1 = inputs + (size_t)min(batch0 + c1i, batch - 1) * (SEQ * INP) + i1;

    float cst[2 * NTL];
#pragma unroll
    for (int q = 0; q < 2 * NTL; ++q) cst[q] = 0.f;

    __syncthreads();

    for (int s = 0; s < SEQ; ++s) {
        // prefetch next x
        float xv0 = 0.f, xv1 = 0.f;
        const bool dox = (s + 1 < SEQ);
        if (dox) {
            xv0 = __ldg(xp0 + (size_t)(s + 1) * INP);
            if (hq1) xv1 = __ldg(xp1 + (size_t)(s + 1) * INP);
        }

        const __nv_bfloat16* BH = sm.B[s & 1][0];
        const __nv_bfloat16* BL = sm.B[s & 1][1];
        __nv_bfloat16* WH = sm.B[(s + 1) & 1][0];
        __nv_bfloat16* WL = sm.B[(s + 1) & 1][1];

        float cacc[2][NTL][4];

        // Epilogue for one n-tile: cells (j=jm, col = nt*8 + 2tig + q)
#define EPILOGUE(nt)                                                          \
        {                                                                     \
            _Pragma("unroll")                                                 \
            for (int q = 0; q < 2; ++q) {                                     \
                const float gi = cacc[0][nt][q];                              \
                const float gf = cacc[0][nt][2 + q];                          \
                const float gg = cacc[1][nt][q];                              \
                const float go = cacc[1][nt][2 + q];                          \
                const float ig = sigmoid_f(gi);                               \
                const float fg = sigmoid_f(gf);                               \
                const float gt = tanh_f(gg);                                  \
                const float og = sigmoid_f(go);                               \
                const int  ci = (nt) * 2 + q;                                 \
                const float cn = fg * cst[ci] + ig * gt;                      \
                cst[ci] = cn;                                                 \
                const float hv = og * tanh_f(cn);                             \
                float hh, hl; split2(hv, hh, hl);                             \
                const int col = (nt) * 8 + 2 * tig + q;                       \
                WH[col * BPAD + jm] = __float2bfloat16(hh);                   \
                WL[col * BPAD + jm] = __float2bfloat16(hl);                   \
            }                                                                 \
        }

        // Fused loop: MMA(nt) issues, then epilogue(nt-1) rides the idle
        // issue slots while nt's HMMAs drain through the tensor pipe.
#pragma unroll
        for (int nt = 0; nt < NTL; ++nt) {
            const int ncol = nt * 8 + gid;
            const uint32_t* colH = (const uint32_t*)(BH + ncol * BPAD);
            const uint32_t* colL = (const uint32_t*)(BL + ncol * BPAD);
            uint32_t bh[KTL][2], bl[KTL][2];
#pragma unroll
            for (int kt = 0; kt < KTL; ++kt) {
                bh[kt][0] = colH[kt * 8 + tig];
                bh[kt][1] = colH[kt * 8 + tig + 4];
                bl[kt][0] = colL[kt * 8 + tig];
                bl[kt][1] = colL[kt * 8 + tig + 4];
            }
#pragma unroll
            for (int mt = 0; mt < 2; ++mt) {
#pragma unroll
                for (int q = 0; q < 4; ++q) cacc[mt][nt][q] = 0.f;
#pragma unroll
                for (int kt = 0; kt < KTL; ++kt) {
                    mma16816(cacc[mt][nt], ahi[mt][kt], bh[kt]);
                    mma16816(cacc[mt][nt], ahi[mt][kt], bl[kt]);
                    mma16816(cacc[mt][nt], alo[mt][kt], bh[kt]);
                }
            }
            if (nt > 0) EPILOGUE(nt - 1);
        }
        EPILOGUE(NTL - 1);
#undef EPILOGUE

        // stash next x into next-parity buffer
        if (dox) {
            float xh, xl;
            split2(xv0, xh, xl);
            WH[c0i * BPAD + HID + i0] = __float2bfloat16(xh);
            WL[c0i * BPAD + HID + i0] = __float2bfloat16(xl);
            if (hq1) {
                split2(xv1, xh, xl);
                WH[c1i * BPAD + HID + i1] = __float2bfloat16(xh);
                WL[c1i * BPAD + HID + i1] = __float2bfloat16(xl);
            }
        }
        __syncthreads();
    }

    // ---- final FC + leaky ReLU; h(512) is in parity-0 buffer (hi+lo)
    const __nv_bfloat16* FH = sm.B[0][0];
    const __nv_bfloat16* FL = sm.B[0][1];
    const float fw0 = fc_w[lane], fw1 = fc_w[lane + 32];
    const float fb  = fc_b[0];
#pragma unroll
    for (int q = 0; q < NTL; ++q) {
        const int col = w * NTL + q;
        float hA = __bfloat162float(FH[col * BPAD + lane])
                 + __bfloat162float(FL[col * BPAD + lane]);
        float hB = __bfloat162float(FH[col * BPAD + lane + 32])
                 + __bfloat162float(FL[col * BPAD + lane + 32]);
        float p = hA * fw0 + hB * fw1;
#pragma unroll
        for (int off = 16; off > 0; off >>= 1)
            p += __shfl_xor_sync(0xffffffffu, p, off);
        if (lane == 0) {
            const int row = batch0 + col;
            if (row < batch) {
                const float v = p + fb;
                out[row] = (v >= 0.f) ? v : 0.01f * v;
            }
        }
    }
}

extern "C" void kernel_launch(void* const* d_in, const int* in_sizes, int n_in,
                              void* d_out, int out_size) {
    const float* inputs = (const float*)d_in[0];
    const float* W_ih   = (const float*)d_in[1];
    const float* W_hh   = (const float*)d_in[2];
    const float* b_ih   = (const float*)d_in[3];
    const float* b_hh   = (const float*)d_in[4];
    const float* fc_w   = (const float*)d_in[5];
    const float* fc_b   = (const float*)d_in[6];
    float*       out    = (float*)d_out;

    const int batch = in_sizes[0] / (SEQ * INP);      // 8192
    const int grid  = (batch + NB - 1) / NB;          // 147

    lstm_hmma_kernel<<<grid, THREADS>>>(inputs, W_ih, W_hh, b_ih, b_hh,
                                        fc_w, fc_b, out, batch);
}

// round 9
// speedup vs baseline: 2.8371x; 1.0552x over previous
#include <cuda_runtime.h>
#include <cuda_bf16.h>
#include <cstdint>

#define SEQ     512
#define INP     5
#define HID     64
#define NB      56          // batch cols per CTA
#define NTL     7           // n-tiles (8 cols each)
#define KT16    4           // full k16 tiles (k=0..63)
#define BPAD    88          // bf16 per B column (44 words = 12 mod 32: conflict-free)
#define THREADS 256

struct SmemT {
    __align__(16) __nv_bfloat16 B[2][2][NB * BPAD];  // [parity][0=hi,1=lo][col][k]
};

__device__ __forceinline__ uint32_t pack_bf16(float lo, float hi) {
    __nv_bfloat162 t = __floats2bfloat162_rn(lo, hi);   // .x=lo (lower 16 bits)
    return *(uint32_t*)&t;
}
__device__ __forceinline__ void split2(float v, float& hi, float& lo) {
    hi = __bfloat162float(__float2bfloat16(v));
    lo = v - hi;
}

// Hardware tanh (sm_75+): 1 MUFU op, max err ~1e-4 abs
__device__ __forceinline__ float tanh_hw(float x) {
    float y;
    asm("tanh.approx.f32 %0, %1;" : "=f"(y) : "f"(x));
    return y;
}
__device__ __forceinline__ float sigmoid_f(float x) {
    return fmaf(tanh_hw(0.5f * x), 0.5f, 0.5f);
}
__device__ __forceinline__ float tanh_f(float x) { return tanh_hw(x); }

// mma.sync m16n8k16 row.col bf16 -> f32, D += A*B
__device__ __forceinline__ void mma16816(float* c, const uint32_t* a, const uint32_t* b) {
    asm volatile(
        "mma.sync.aligned.m16n8k16.row.col.f32.bf16.bf16.f32 "
        "{%0,%1,%2,%3}, {%4,%5,%6,%7}, {%8,%9}, {%0,%1,%2,%3};"
        : "+f"(c[0]), "+f"(c[1]), "+f"(c[2]), "+f"(c[3])
        : "r"(a[0]), "r"(a[1]), "r"(a[2]), "r"(a[3]), "r"(b[0]), "r"(b[1]));
}
// mma.sync m16n8k8 row.col bf16 -> f32, D += A*B (K-tail tile)
__device__ __forceinline__ void mma1688(float* c, const uint32_t* a, uint32_t b) {
    asm volatile(
        "mma.sync.aligned.m16n8k8.row.col.f32.bf16.bf16.f32 "
        "{%0,%1,%2,%3}, {%4,%5}, {%6}, {%0,%1,%2,%3};"
        : "+f"(c[0]), "+f"(c[1]), "+f"(c[2]), "+f"(c[3])
        : "r"(a[0]), "r"(a[1]), "r"(b));
}

// Extended weight matrix element: W_ext[m][k], m permuted so that within a
// warp's m-pair (tiles 2w, 2w+1) each thread's 4 C rows = i,f,g,o of one j.
//   j = (m>>5)*8 + (m&7),  g = 2*((m>>4)&1) + ((m>>3)&1)
__device__ float wext(const float* W_hh, const float* W_ih,
                      const float* b_ih, const float* b_hh, int m, int k) {
    int j   = ((m >> 5) << 3) | (m & 7);
    int g   = (((m >> 4) & 1) << 1) | ((m >> 3) & 1);
    int row = g * HID + j;
    if (k < HID)            return W_hh[row * HID + k];
    if (k < HID + INP)      return W_ih[row * INP + (k - HID)];
    if (k == HID + INP)     return b_ih[row] + b_hh[row];   // bias column
    return 0.f;
}

// ---------------------------------------------------------------------------
// HMMA LSTM (verified R8 structure). Two deltas vs R8:
//  1) K-extension trimmed 80->72: 4 x m16n8k16 + 1 x m16n8k8 per split term
//     (identical math, zero-pad columns dropped) -> -10% tensor work.
//  2) B fragments software-pipelined: tile nt+1's LDS issue before tile nt's
//     MMA burst, hiding crossbar queue + latency under tensor drain.
// ---------------------------------------------------------------------------
__global__ void __launch_bounds__(THREADS, 1)
lstm_hmma_kernel(const float* __restrict__ inputs,  // [B, SEQ, INP]
                 const float* __restrict__ W_ih,    // [256, INP]
                 const float* __restrict__ W_hh,    // [256, HID]
                 const float* __restrict__ b_ih,    // [256]
                 const float* __restrict__ b_hh,    // [256]
                 const float* __restrict__ fc_w,    // [1, HID]
                 const float* __restrict__ fc_b,    // [1]
                 float* __restrict__ out,           // [B, 1]
                 int batch)
{
    __shared__ SmemT sm;

    const int t    = threadIdx.x;
    const int lane = t & 31;
    const int w    = t >> 5;
    const int gid  = lane >> 2;          // fragment row group 0..7
    const int tig  = lane & 3;           // fragment col group 0..3
    const int jm   = (w << 3) | gid;     // this thread's hidden index
    const int batch0 = blockIdx.x * NB;

    // ---- init smem: zero all buffers, set bias row (k=69) = 1.0 in hi bufs
    for (int idx = t; idx < 2 * 2 * NB * BPAD / 2; idx += THREADS)
        ((uint32_t*)sm.B)[idx] = 0u;
    __syncthreads();
    if (t < NB) {
        sm.B[0][0][t * BPAD + HID + INP] = __float2bfloat16(1.0f);
        sm.B[1][0][t * BPAD + HID + INP] = __float2bfloat16(1.0f);
    }

    // x(0) into parity-0 buffer rows 64..68
    for (int q = t; q < NB * INP; q += THREADS) {
        int col = q / INP, i = q - col * INP;
        int row = min(batch0 + col, batch - 1);
        float xv = inputs[(size_t)row * (SEQ * INP) + i];
        float xh, xl; split2(xv, xh, xl);
        sm.B[0][0][col * BPAD + HID + i] = __float2bfloat16(xh);
        sm.B[0][1][col * BPAD + HID + i] = __float2bfloat16(xl);
    }

    // ---- load W_ext fragments into registers (hi/lo), one-time
    uint32_t ahi[2][KT16][4], alo[2][KT16][4];   // k16 tiles, k=0..63
    uint32_t ahi8[2][2], alo8[2][2];             // k8 tail, k=64..71
#pragma unroll
    for (int mt = 0; mt < 2; ++mt) {
        const int mbase = ((w << 1) | mt) << 4;
#pragma unroll
        for (int kt = 0; kt < KT16; ++kt) {
#pragma unroll
            for (int cp = 0; cp < 2; ++cp) {          // col pair: k+0/1 or k+8/9
#pragma unroll
                for (int rr = 0; rr < 2; ++rr) {      // row gid or gid+8
                    int m  = mbase + gid + rr * 8;
                    int k0 = kt * 16 + 2 * tig + cp * 8;
                    float v0 = wext(W_hh, W_ih, b_ih, b_hh, m, k0);
                    float v1 = wext(W_hh, W_ih, b_ih, b_hh, m, k0 + 1);
                    float h0, l0, h1, l1;
                    split2(v0, h0, l0);
                    split2(v1, h1, l1);
                    ahi[mt][kt][cp * 2 + rr] = pack_bf16(h0, h1);
                    alo[mt][kt][cp * 2 + rr] = pack_bf16(l0, l1);
                }
            }
        }
        // k8 tail: k = 64 + 2*tig (+1)
#pragma unroll
        for (int rr = 0; rr < 2; ++rr) {
            int m  = mbase + gid + rr * 8;
            int k0 = 64 + 2 * tig;
            float v0 = wext(W_hh, W_ih, b_ih, b_hh, m, k0);
            float v1 = wext(W_hh, W_ih, b_ih, b_hh, m, k0 + 1);
            float h0, l0, h1, l1;
            split2(v0, h0, l0);
            split2(v1, h1, l1);
            ahi8[mt][rr] = pack_bf16(h0, h1);
            alo8[mt][rr] = pack_bf16(l0, l1);
        }
    }

    // x prefetch ownership: indices t and t+256 (< NB*INP = 280)
    const int  q1   = t + THREADS;
    const bool hq1  = q1 < NB * INP;
    const int  c0i  = t / INP,  i0 = t - c0i * INP;
    const int  c1i  = hq1 ? q1 / INP : 0, i1 = hq1 ? q1 - c1i * INP : 0;
    const float* xp0 = inputs + (size_t)min(batch0 + c0i, batch - 1) * (SEQ * INP) + i0;
    const float* xp1 = inputs + (size_t)min(batch0 + c1i, batch - 1) * (SEQ * INP) + i1;

    float cst[2 * NTL];
#pragma unroll
    for (int q = 0; q < 2 * NTL; ++q) cst[q] = 0.f;

    __syncthreads();

    for (int s = 0; s < SEQ; ++s) {
        // prefetch next x
        float xv0 = 0.f, xv1 = 0.f;
        const bool dox = (s + 1 < SEQ);
        if (dox) {
            xv0 = __ldg(xp0 + (size_t)(s + 1) * INP);
            if (hq1) xv1 = __ldg(xp1 + (size_t)(s + 1) * INP);
        }

        const __nv_bfloat16* BH = sm.B[s & 1][0];
        const __nv_bfloat16* BL = sm.B[s & 1][1];
        __nv_bfloat16* WH = sm.B[(s + 1) & 1][0];
        __nv_bfloat16* WL = sm.B[(s + 1) & 1][1];

        float cacc[2][NTL][4];

        // B fragments, double-buffered across n-tiles
        uint32_t bh[2][KT16][2], bl[2][KT16][2], b8h[2], b8l[2];

#define LOADFRAG(buf, nt)                                                     \
        {                                                                     \
            const int ncol = (nt) * 8 + gid;                                  \
            const uint32_t* colH = (const uint32_t*)(BH + ncol * BPAD);       \
            const uint32_t* colL = (const uint32_t*)(BL + ncol * BPAD);       \
            _Pragma("unroll")                                                 \
            for (int kt = 0; kt < KT16; ++kt) {                               \
                bh[buf][kt][0] = colH[kt * 8 + tig];                          \
                bh[buf][kt][1] = colH[kt * 8 + tig + 4];                      \
                bl[buf][kt][0] = colL[kt * 8 + tig];                          \
                bl[buf][kt][1] = colL[kt * 8 + tig + 4];                      \
            }                                                                 \
            b8h[buf] = colH[32 + tig];                                        \
            b8l[buf] = colL[32 + tig];                                        \
        }

        // Epilogue for one n-tile: cells (j=jm, col = nt*8 + 2tig + q)
#define EPILOGUE(nt)                                                          \
        {                                                                     \
            _Pragma("unroll")                                                 \
            for (int q = 0; q < 2; ++q) {                                     \
                const float gi = cacc[0][nt][q];                              \
                const float gf = cacc[0][nt][2 + q];                          \
                const float gg = cacc[1][nt][q];                              \
                const float go = cacc[1][nt][2 + q];                          \
                const float ig = sigmoid_f(gi);                               \
                const float fg = sigmoid_f(gf);                               \
                const float gt = tanh_f(gg);                                  \
                const float og = sigmoid_f(go);                               \
                const int  ci = (nt) * 2 + q;                                 \
                const float cn = fg * cst[ci] + ig * gt;                      \
                cst[ci] = cn;                                                 \
                const float hv = og * tanh_f(cn);                             \
                float hh, hl; split2(hv, hh, hl);                             \
                const int col = (nt) * 8 + 2 * tig + q;                       \
                WH[col * BPAD + jm] = __float2bfloat16(hh);                   \
                WL[col * BPAD + jm] = __float2bfloat16(hl);                   \
            }                                                                 \
        }

        LOADFRAG(0, 0);
#pragma unroll
        for (int nt = 0; nt < NTL; ++nt) {
            const int cur = nt & 1, nxt = cur ^ 1;
            // pipeline: next tile's LDS issue before this tile's MMA burst
            if (nt + 1 < NTL) LOADFRAG(nxt, nt + 1);

#pragma unroll
            for (int mt = 0; mt < 2; ++mt)
#pragma unroll
                for (int q = 0; q < 4; ++q) cacc[mt][nt][q] = 0.f;

            // mt-interleaved issue: two independent accumulator chains
#pragma unroll
            for (int kt = 0; kt < KT16; ++kt) {
                mma16816(cacc[0][nt], ahi[0][kt], bh[cur][kt]);
                mma16816(cacc[1][nt], ahi[1][kt], bh[cur][kt]);
                mma16816(cacc[0][nt], ahi[0][kt], bl[cur][kt]);
                mma16816(cacc[1][nt], ahi[1][kt], bl[cur][kt]);
                mma16816(cacc[0][nt], alo[0][kt], bh[cur][kt]);
                mma16816(cacc[1][nt], alo[1][kt], bh[cur][kt]);
            }
            mma1688(cacc[0][nt], ahi8[0], b8h[cur]);
            mma1688(cacc[1][nt], ahi8[1], b8h[cur]);
            mma1688(cacc[0][nt], ahi8[0], b8l[cur]);
            mma1688(cacc[1][nt], ahi8[1], b8l[cur]);
            mma1688(cacc[0][nt], alo8[0], b8h[cur]);
            mma1688(cacc[1][nt], alo8[1], b8h[cur]);

            if (nt > 0) EPILOGUE(nt - 1);
        }
        EPILOGUE(NTL - 1);
#undef EPILOGUE
#undef LOADFRAG

        // stash next x into next-parity buffer
        if (dox) {
            float xh, xl;
            split2(xv0, xh, xl);
            WH[c0i * BPAD + HID + i0] = __float2bfloat16(xh);
            WL[c0i * BPAD + HID + i0] = __float2bfloat16(xl);
            if (hq1) {
                split2(xv1, xh, xl);
                WH[c1i * BPAD + HID + i1] = __float2bfloat16(xh);
                WL[c1i * BPAD + HID + i1] = __float2bfloat16(xl);
            }
        }
        __syncthreads();
    }

    // ---- final FC + leaky ReLU; h(512) is in parity-0 buffer (hi+lo)
    const __nv_bfloat16* FH = sm.B[0][0];
    const __nv_bfloat16* FL = sm.B[0][1];
    const float fw0 = fc_w[lane], fw1 = fc_w[lane + 32];
    const float fb  = fc_b[0];
#pragma unroll
    for (int q = 0; q < NTL; ++q) {
        const int col = w * NTL + q;
        float hA = __bfloat162float(FH[col * BPAD + lane])
                 + __bfloat162float(FL[col * BPAD + lane]);
        float hB = __bfloat162float(FH[col * BPAD + lane + 32])
                 + __bfloat162float(FL[col * BPAD + lane + 32]);
        float p = hA * fw0 + hB * fw1;
#pragma unroll
        for (int off = 16; off > 0; off >>= 1)
            p += __shfl_xor_sync(0xffffffffu, p, off);
        if (lane == 0) {
            const int row = batch0 + col;
            if (row < batch) {
                const float v = p + fb;
                out[row] = (v >= 0.f) ? v : 0.01f * v;
            }
        }
    }
}

extern "C" void kernel_launch(void* const* d_in, const int* in_sizes, int n_in,
                              void* d_out, int out_size) {
    const float* inputs = (const float*)d_in[0];
    const float* W_ih   = (const float*)d_in[1];
    const float* W_hh   = (const float*)d_in[2];
    const float* b_ih   = (const float*)d_in[3];
    const float* b_hh   = (const float*)d_in[4];
    const float* fc_w   = (const float*)d_in[5];
    const float* fc_b   = (const float*)d_in[6];
    float*       out    = (float*)d_out;

    const int batch = in_sizes[0] / (SEQ * INP);      // 8192
    const int grid  = (batch + NB - 1) / NB;          // 147

    lstm_hmma_kernel<<<grid, THREADS>>>(inputs, W_ih, W_hh, b_ih, b_hh,
                                        fc_w, fc_b, out, batch);
}